// round 4
// baseline (speedup 1.0000x reference)
#include <cuda_runtime.h>
#include <math.h>

// Problem constants
#define Bn   8
#define Cin  128
#define Cout 128
#define Hn   112
#define Wn   112
#define Kk   9
#define HW   (Hn*Wn)            // 12544
#define NPIX (Bn*HW)            // 100352
#define KDIM (Cin*Kk)           // 1152

// ---------------- device scratch (no runtime alloc allowed) ----------------
__device__ float4 g_wT4[KDIM*32];            // [kk][o/4] : w transposed, 590KB
__device__ float  g_owT[KDIM*28];            // offset+mask weights, [kk][m(28, padded)]
__device__ float4 g_meta_w[NPIX*Kk];         // bilinear tap weights (mask folded)
__device__ int4   g_meta_off[NPIX*Kk];       // clamped plane offsets y*W+x

// ---------------- packed f32x2 helpers (sm_103a FFMA2) ----------------
static __device__ __forceinline__ unsigned long long pk2(float lo, float hi) {
    unsigned long long r;
    asm("mov.b64 %0, {%1, %2};" : "=l"(r) : "f"(lo), "f"(hi));
    return r;
}
static __device__ __forceinline__ void fma2(unsigned long long& acc,
                                            unsigned long long a,
                                            unsigned long long b) {
    asm("fma.rn.f32x2 %0, %1, %2, %0;" : "+l"(acc) : "l"(a), "l"(b));
}
static __device__ __forceinline__ float2 upk2(unsigned long long v) {
    float2 r;
    asm("mov.b64 {%0, %1}, %2;" : "=f"(r.x), "=f"(r.y) : "l"(v));
    return r;
}

// ---------------- kernel 0: weight repack ----------------
__global__ void prep_weights_kernel(const float* __restrict__ w,
                                    const float* __restrict__ ow,
                                    const float* __restrict__ mw) {
    int idx = blockIdx.x * 256 + threadIdx.x;
    if (idx < KDIM * 128) {
        int kk = idx >> 7, o = idx & 127;
        ((float*)g_wT4)[idx] = w[o * KDIM + kk];
    }
    if (idx < KDIM * 28) {
        int kk = idx / 28, m = idx - (idx / 28) * 28;
        float v = 0.f;
        if (m < 18)      v = ow[m * KDIM + kk];
        else if (m < 27) v = mw[(m - 18) * KDIM + kk];
        g_owT[idx] = v;
    }
}

// ---------------- kernel 1: offset/mask conv -> sampling metadata ----------------
__global__ void __launch_bounds__(128)
offmask_kernel(const float* __restrict__ x,
               const float* __restrict__ ob,
               const float* __restrict__ mb) {
    __shared__ __align__(16) float s_w[16 * 9 * 28];   // 16KB
    const int tid = threadIdx.x;
    const int pix = blockIdx.x * 128 + tid;
    const int b = pix / HW;
    const int rem = pix - b * HW;
    const int h = rem / Wn;
    const int wc = rem - h * Wn;
    const float* xb = x + (size_t)b * Cin * HW;

    // 14 packed accumulators (28 outputs: 18 offset + 9 mask + 1 pad)
    unsigned long long A[14];
#pragma unroll
    for (int j = 0; j < 14; j++) {
        int m0 = 2 * j, m1 = 2 * j + 1;
        float lo = (m0 < 18) ? __ldg(ob + m0) : ((m0 < 27) ? __ldg(mb + m0 - 18) : 0.f);
        float hi = (m1 < 18) ? __ldg(ob + m1) : ((m1 < 27) ? __ldg(mb + m1 - 18) : 0.f);
        A[j] = pk2(lo, hi);
    }

    for (int c0 = 0; c0 < Cin; c0 += 16) {
        __syncthreads();
        for (int i = tid; i < 4032; i += 128) s_w[i] = g_owT[c0 * 252 + i];
        __syncthreads();
#pragma unroll 4
        for (int cc = 0; cc < 16; ++cc) {
            const float* xc = xb + (c0 + cc) * HW;
            float tap[9];
#pragma unroll
            for (int di = 0; di < 3; di++)
#pragma unroll
                for (int dj = 0; dj < 3; dj++) {
                    int y = h - 1 + di, xx = wc - 1 + dj;
                    bool ok = ((unsigned)y < (unsigned)Hn) && ((unsigned)xx < (unsigned)Wn);
                    tap[di * 3 + dj] = ok ? __ldg(xc + y * Wn + xx) : 0.f;
                }
#pragma unroll
            for (int k = 0; k < 9; k++) {
                unsigned long long xv2 = pk2(tap[k], tap[k]);
                const double2* wr = (const double2*)&s_w[(cc * 9 + k) * 28];
#pragma unroll
                for (int q = 0; q < 7; q++) {
                    double2 wv = wr[q];
                    fma2(A[2 * q],     __double_as_longlong(wv.x), xv2);
                    fma2(A[2 * q + 1], __double_as_longlong(wv.y), xv2);
                }
            }
        }
    }

    // unpack accumulators
    float a[28];
#pragma unroll
    for (int j = 0; j < 14; j++) {
        float2 v = upk2(A[j]);
        a[2 * j] = v.x; a[2 * j + 1] = v.y;
    }

    // epilogue: build per-(pixel,k) bilinear metadata
#pragma unroll
    for (int k = 0; k < 9; k++) {
        float dy = a[2 * k], dx = a[2 * k + 1];
        float mraw = a[18 + k];
        float mval = 2.f / (1.f + expf(-mraw));
        int ki = k / 3, kj = k - ki * 3;
        float ys = (float)(h - 1 + ki) + dy;
        float xs = (float)(wc - 1 + kj) + dx;
        float y0f = floorf(ys), x0f = floorf(xs);
        float ly = ys - y0f, lx = xs - x0f;
        int y0 = (int)y0f, x0 = (int)x0f;
        int y1 = y0 + 1, x1 = x0 + 1;
        float vy0 = ((unsigned)y0 < (unsigned)Hn) ? 1.f : 0.f;
        float vy1 = ((unsigned)y1 < (unsigned)Hn) ? 1.f : 0.f;
        float vx0 = ((unsigned)x0 < (unsigned)Wn) ? 1.f : 0.f;
        float vx1 = ((unsigned)x1 < (unsigned)Wn) ? 1.f : 0.f;
        float w00 = mval * (1.f - ly) * (1.f - lx) * vy0 * vx0;
        float w01 = mval * (1.f - ly) * lx          * vy0 * vx1;
        float w10 = mval * ly          * (1.f - lx) * vy1 * vx0;
        float w11 = mval * ly          * lx          * vy1 * vx1;
        int y0c = min(max(y0, 0), Hn - 1), y1c = min(max(y1, 0), Hn - 1);
        int x0c = min(max(x0, 0), Wn - 1), x1c = min(max(x1, 0), Wn - 1);
        int oy0 = y0c * Wn, oy1 = y1c * Wn;
        g_meta_w[pix * 9 + k]   = make_float4(w00, w01, w10, w11);
        g_meta_off[pix * 9 + k] = make_int4(oy0 + x0c, oy0 + x1c, oy1 + x0c, oy1 + x1c);
    }
}

// ---------------- kernel 2: fused bilinear-sample + GEMM (FFMA2 core) ----------------
// Block: 256 threads, 64 pixels x 128 output channels.
// warp id og (0..7): owns 16 consecutive o-channels (og*16..+15), as 8 f32x2 pairs
// lane (0..31): pixels {lane, lane+32}
__global__ void __launch_bounds__(256)
main_kernel(const float* __restrict__ x,
            const float* __restrict__ bias,
            float* __restrict__ out) {
    __shared__ float4 s_mw[576];
    __shared__ int4   s_mo[576];
    __shared__ float  s_s[36 * 64];

    const int tid = threadIdx.x;
    const int pix0 = blockIdx.x * 64;
    const int b = pix0 / HW;
    const int hw0 = pix0 - b * HW;
    const int lane = tid & 31;
    const int og = tid >> 5;
    const int p_s = tid & 63;
    const int kk0 = tid >> 6;

    // load sampling metadata for 64 pixels x 9 taps
    for (int i = tid; i < 576; i += 256) {
        s_mw[i] = g_meta_w[pix0 * 9 + i];
        s_mo[i] = g_meta_off[pix0 * 9 + i];
    }
    __syncthreads();

    const float* xb = x + (size_t)b * Cin * HW;
    unsigned long long A0[8], A1[8];
#pragma unroll
    for (int q = 0; q < 8; q++) { A0[q] = 0ull; A1[q] = 0ull; }

    for (int c0 = 0; c0 < Cin; c0 += 4) {
        // ---- cooperative bilinear sampling: s_s[kkl][p], kkl = cc*9+k ----
#pragma unroll
        for (int i = 0; i < 9; ++i) {
            int kkl = kk0 + i * 4;          // 0..35, warp-uniform
            int cc = kkl / 9;
            int k = kkl - cc * 9;
            const float* xc = xb + (c0 + cc) * HW;
            int mi = p_s * 9 + k;
            float4 wv = s_mw[mi];
            int4 ov = s_mo[mi];
            float s = wv.x * __ldg(xc + ov.x) + wv.y * __ldg(xc + ov.y)
                    + wv.z * __ldg(xc + ov.z) + wv.w * __ldg(xc + ov.w);
            s_s[kkl * 64 + p_s] = s;
        }
        __syncthreads();

        // ---- GEMM micro-tile: packed f32x2 FMAs ----
#pragma unroll 4
        for (int kkl = 0; kkl < 36; ++kkl) {
            float s0 = s_s[kkl * 64 + lane];
            float s1 = s_s[kkl * 64 + 32 + lane];
            unsigned long long S0 = pk2(s0, s0);
            unsigned long long S1 = pk2(s1, s1);
            const double2* wr = (const double2*)((const float*)g_wT4
                                + (size_t)(c0 * 9 + kkl) * 128 + og * 16);
#pragma unroll
            for (int q = 0; q < 4; ++q) {
                double2 wv = __ldg(wr + q);
                unsigned long long wlo = __double_as_longlong(wv.x);
                unsigned long long whi = __double_as_longlong(wv.y);
                fma2(A0[q * 2],     wlo, S0);
                fma2(A0[q * 2 + 1], whi, S0);
                fma2(A1[q * 2],     wlo, S1);
                fma2(A1[q * 2 + 1], whi, S1);
            }
        }
        __syncthreads();
    }

    // ---- epilogue: coalesced stores (lanes span consecutive pixels) ----
    float* obp = out + (size_t)b * Cout * HW + hw0 + lane;
#pragma unroll
    for (int q = 0; q < 8; q++) {
        float2 v0 = upk2(A0[q]);
        float2 v1 = upk2(A1[q]);
        int o = og * 16 + q * 2;
        float b0 = __ldg(bias + o);
        float b1 = __ldg(bias + o + 1);
        obp[(size_t)o * HW]            = v0.x + b0;
        obp[(size_t)o * HW + 32]       = v1.x + b0;
        obp[(size_t)(o + 1) * HW]      = v0.y + b1;
        obp[(size_t)(o + 1) * HW + 32] = v1.y + b1;
    }
}

// ---------------- launcher ----------------
extern "C" void kernel_launch(void* const* d_in, const int* in_sizes, int n_in,
                              void* d_out, int out_size) {
    const float* x        = (const float*)d_in[0];
    const float* offset_w = (const float*)d_in[1];
    const float* offset_b = (const float*)d_in[2];
    const float* mod_w    = (const float*)d_in[3];
    const float* mod_b    = (const float*)d_in[4];
    const float* w        = (const float*)d_in[5];
    const float* bias     = (const float*)d_in[6];
    float* out = (float*)d_out;

    prep_weights_kernel<<<(KDIM * 128 + 255) / 256, 256>>>(w, offset_w, mod_w);
    offmask_kernel<<<NPIX / 128, 128>>>(x, offset_b, mod_b);
    main_kernel<<<NPIX / 64, 256>>>(x, bias, out);
}

// round 5
// speedup vs baseline: 2.5300x; 2.5300x over previous
#include <cuda_runtime.h>
#include <math.h>

// Problem constants
#define Bn   8
#define Cin  128
#define Cout 128
#define Hn   112
#define Wn   112
#define Kk   9
#define HW   (Hn*Wn)            // 12544
#define NPIX (Bn*HW)            // 100352
#define KDIM (Cin*Kk)           // 1152

#define KC   72                 // K-values per chunk (8 channels x 9 taps)
#define KST  76                 // smem K-stride (76 % 32 == 12 -> conflict-free frags)

// ---------------- device scratch (no runtime alloc allowed) ----------------
__device__ float  g_wTT[Cout*KDIM];          // tf32-rounded main weights, [o][kk]
__device__ float  g_owT[KDIM*28];            // offset+mask weights, [kk][m(28, padded)]
__device__ float4 g_meta_w[NPIX*Kk];         // bilinear tap weights (mask folded)
__device__ int4   g_meta_off[NPIX*Kk];       // clamped plane offsets y*W+x

static __device__ __forceinline__ float to_tf32(float x) {
    float r;
    asm("cvt.rna.tf32.f32 %0, %1;" : "=f"(r) : "f"(x));
    return r;
}

// ---------------- kernel 0: weight prep ----------------
__global__ void prep_weights_kernel(const float* __restrict__ w,
                                    const float* __restrict__ ow,
                                    const float* __restrict__ mw) {
    int idx = blockIdx.x * 256 + threadIdx.x;
    if (idx < Cout * KDIM) {
        g_wTT[idx] = to_tf32(w[idx]);        // same [o][kk] layout, tf32-rounded
    }
    if (idx < KDIM * 28) {
        int kk = idx / 28, m = idx - (idx / 28) * 28;
        float v = 0.f;
        if (m < 18)      v = ow[m * KDIM + kk];
        else if (m < 27) v = mw[(m - 18) * KDIM + kk];
        g_owT[idx] = v;
    }
}

// ---------------- kernel 1: offset/mask conv -> sampling metadata (fp32, R3) ----------------
__global__ void __launch_bounds__(128)
offmask_kernel(const float* __restrict__ x,
               const float* __restrict__ ob,
               const float* __restrict__ mb) {
    __shared__ __align__(16) float s_w[16 * 9 * 28];   // 16KB
    const int tid = threadIdx.x;
    const int pix = blockIdx.x * 128 + tid;
    const int b = pix / HW;
    const int rem = pix - b * HW;
    const int h = rem / Wn;
    const int wc = rem - h * Wn;
    const float* xb = x + (size_t)b * Cin * HW;

    float a[28];
#pragma unroll
    for (int m = 0; m < 28; m++)
        a[m] = (m < 18) ? __ldg(ob + m) : ((m < 27) ? __ldg(mb + m - 18) : 0.f);

    for (int c0 = 0; c0 < Cin; c0 += 16) {
        __syncthreads();
        for (int i = tid; i < 4032; i += 128) s_w[i] = g_owT[c0 * 252 + i];
        __syncthreads();
#pragma unroll 4
        for (int cc = 0; cc < 16; ++cc) {
            const float* xc = xb + (c0 + cc) * HW;
            float tap[9];
#pragma unroll
            for (int di = 0; di < 3; di++)
#pragma unroll
                for (int dj = 0; dj < 3; dj++) {
                    int y = h - 1 + di, xx = wc - 1 + dj;
                    bool ok = ((unsigned)y < (unsigned)Hn) && ((unsigned)xx < (unsigned)Wn);
                    tap[di * 3 + dj] = ok ? __ldg(xc + y * Wn + xx) : 0.f;
                }
#pragma unroll
            for (int k = 0; k < 9; k++) {
                float xv = tap[k];
                const float4* wr = (const float4*)&s_w[(cc * 9 + k) * 28];
#pragma unroll
                for (int q = 0; q < 7; q++) {
                    float4 wv = wr[q];
                    a[q * 4 + 0] += xv * wv.x;
                    a[q * 4 + 1] += xv * wv.y;
                    a[q * 4 + 2] += xv * wv.z;
                    a[q * 4 + 3] += xv * wv.w;
                }
            }
        }
    }

#pragma unroll
    for (int k = 0; k < 9; k++) {
        float dy = a[2 * k], dx = a[2 * k + 1];
        float mraw = a[18 + k];
        float mval = 2.f / (1.f + expf(-mraw));
        int ki = k / 3, kj = k - ki * 3;
        float ys = (float)(h - 1 + ki) + dy;
        float xs = (float)(wc - 1 + kj) + dx;
        float y0f = floorf(ys), x0f = floorf(xs);
        float ly = ys - y0f, lx = xs - x0f;
        int y0 = (int)y0f, x0 = (int)x0f;
        int y1 = y0 + 1, x1 = x0 + 1;
        float vy0 = ((unsigned)y0 < (unsigned)Hn) ? 1.f : 0.f;
        float vy1 = ((unsigned)y1 < (unsigned)Hn) ? 1.f : 0.f;
        float vx0 = ((unsigned)x0 < (unsigned)Wn) ? 1.f : 0.f;
        float vx1 = ((unsigned)x1 < (unsigned)Wn) ? 1.f : 0.f;
        float w00 = mval * (1.f - ly) * (1.f - lx) * vy0 * vx0;
        float w01 = mval * (1.f - ly) * lx          * vy0 * vx1;
        float w10 = mval * ly          * (1.f - lx) * vy1 * vx0;
        float w11 = mval * ly          * lx          * vy1 * vx1;
        int y0c = min(max(y0, 0), Hn - 1), y1c = min(max(y1, 0), Hn - 1);
        int x0c = min(max(x0, 0), Wn - 1), x1c = min(max(x1, 0), Wn - 1);
        int oy0 = y0c * Wn, oy1 = y1c * Wn;
        g_meta_w[pix * 9 + k]   = make_float4(w00, w01, w10, w11);
        g_meta_off[pix * 9 + k] = make_int4(oy0 + x0c, oy0 + x1c, oy1 + x0c, oy1 + x1c);
    }
}

// ---------------- kernel 2: fused bilinear-sample + TF32 tensor-core GEMM ----------------
// Block: 256 threads = 8 warps, tile = 64 pixels (M) x 128 outputs (N), K = 1152.
// Warp grid 2(M) x 4(N): warp tile 32x32 via 2x4 m16n8k8 tf32 MMA atoms per k-step.
__global__ void __launch_bounds__(256, 2)
main_kernel(const float* __restrict__ x,
            const float* __restrict__ bias,
            float* __restrict__ out) {
    extern __shared__ char dyn[];
    float4* s_mw = (float4*)dyn;                          //  9216 B (576 float4)
    int4*   s_mo = (int4*)(dyn + 9216);                   //  9216 B
    float*  s_s  = (float*)(dyn + 18432);                 // 64*76*4 = 19456 B
    float*  s_w  = (float*)(dyn + 18432 + 19456);         // 128*76*4 = 38912 B

    const int tid  = threadIdx.x;
    const int pix0 = blockIdx.x * 64;
    const int b    = pix0 / HW;
    const int hw0  = pix0 - b * HW;

    // load sampling metadata for 64 pixels x 9 taps
    for (int i = tid; i < 576; i += 256) {
        s_mw[i] = g_meta_w[pix0 * 9 + i];
        s_mo[i] = g_meta_off[pix0 * 9 + i];
    }

    const int lane = tid & 31;
    const int wid  = tid >> 5;
    const int m0   = (wid & 1) * 32;       // warp M offset (pixels)
    const int n0   = (wid >> 1) * 32;      // warp N offset (outputs)
    const int arow = lane >> 2;            // fragment row group
    const int acol = lane & 3;             // fragment k sub-index
    const int sp   = tid >> 2;             // sampling: pixel 0..63
    const int kq   = tid & 3;              // sampling: k phase 0..3

    const float* xb = x + (size_t)b * Cin * HW;
    float acc[2][4][4];
#pragma unroll
    for (int ma = 0; ma < 2; ma++)
#pragma unroll
        for (int na = 0; na < 4; na++)
#pragma unroll
            for (int q = 0; q < 4; q++) acc[ma][na][q] = 0.f;

    __syncthreads();

    for (int c0 = 0; c0 < Cin; c0 += 8) {
        // ---- stage weight chunk: s_w[o][kkl], 128 x 72 tf32 ----
#pragma unroll
        for (int j = 0; j < 9; j++) {
            int idx4 = tid + j * 256;               // 0..2303 float4s
            int o = idx4 / 18, r = idx4 - o * 18;
            float4 v = *(const float4*)(g_wTT + (size_t)o * KDIM + c0 * 9 + r * 4);
            *(float4*)(s_w + o * KST + r * 4) = v;
        }

        // ---- cooperative bilinear sampling: s_s[pix][kkl] (tf32) ----
        {
            int cc = 0, kk = kq;
#pragma unroll
            for (int i = 0; i < 18; i++) {
                const float* xc = xb + (c0 + cc) * HW;
                int mi = sp * 9 + kk;
                float4 wv = s_mw[mi];
                int4  ov = s_mo[mi];
                float s = wv.x * __ldg(xc + ov.x) + wv.y * __ldg(xc + ov.y)
                        + wv.z * __ldg(xc + ov.z) + wv.w * __ldg(xc + ov.w);
                s_s[sp * KST + cc * 9 + kk] = to_tf32(s);
                kk += 4; if (kk >= 9) { kk -= 9; cc++; }
            }
        }
        __syncthreads();

        // ---- MMA phase: 9 k-steps of 8 ----
        const unsigned* ss = (const unsigned*)s_s;
        const unsigned* sw = (const unsigned*)s_w;
#pragma unroll
        for (int ks = 0; ks < 9; ks++) {
            const int ka = ks * 8 + acol;
            unsigned a[2][4];
#pragma unroll
            for (int ma = 0; ma < 2; ma++) {
                int base = (m0 + ma * 16 + arow) * KST + ka;
                a[ma][0] = ss[base];
                a[ma][1] = ss[base + 8 * KST];
                a[ma][2] = ss[base + 4];
                a[ma][3] = ss[base + 8 * KST + 4];
            }
#pragma unroll
            for (int na = 0; na < 4; na++) {
                int bb = (n0 + na * 8 + arow) * KST + ka;
                unsigned b0 = sw[bb], b1 = sw[bb + 4];
#pragma unroll
                for (int ma = 0; ma < 2; ma++) {
                    asm volatile(
                        "mma.sync.aligned.m16n8k8.row.col.f32.tf32.tf32.f32 "
                        "{%0,%1,%2,%3}, {%4,%5,%6,%7}, {%8,%9}, {%0,%1,%2,%3};"
                        : "+f"(acc[ma][na][0]), "+f"(acc[ma][na][1]),
                          "+f"(acc[ma][na][2]), "+f"(acc[ma][na][3])
                        : "r"(a[ma][0]), "r"(a[ma][1]), "r"(a[ma][2]), "r"(a[ma][3]),
                          "r"(b0), "r"(b1));
                }
            }
        }
        __syncthreads();
    }

    // ---- epilogue: fp32 bias add + stores ----
#pragma unroll
    for (int ma = 0; ma < 2; ma++) {
        int prow = hw0 + m0 + ma * 16 + arow;
#pragma unroll
        for (int na = 0; na < 4; na++) {
            int o = n0 + na * 8 + 2 * acol;
            float b0 = __ldg(bias + o);
            float b1 = __ldg(bias + o + 1);
            float* p0 = out + ((size_t)b * Cout + o) * HW + prow;
            float* p1 = p0 + HW;
            p0[0] = acc[ma][na][0] + b0;   // (row,   o)
            p1[0] = acc[ma][na][1] + b1;   // (row,   o+1)
            p0[8] = acc[ma][na][2] + b0;   // (row+8, o)
            p1[8] = acc[ma][na][3] + b1;   // (row+8, o+1)
        }
    }
}

// ---------------- launcher ----------------
extern "C" void kernel_launch(void* const* d_in, const int* in_sizes, int n_in,
                              void* d_out, int out_size) {
    const float* x        = (const float*)d_in[0];
    const float* offset_w = (const float*)d_in[1];
    const float* offset_b = (const float*)d_in[2];
    const float* mod_w    = (const float*)d_in[3];
    const float* mod_b    = (const float*)d_in[4];
    const float* w        = (const float*)d_in[5];
    const float* bias     = (const float*)d_in[6];
    float* out = (float*)d_out;

    const int SMEM = 9216 + 9216 + 19456 + 38912;   // 76800 B
    cudaFuncSetAttribute(main_kernel, cudaFuncAttributeMaxDynamicSharedMemorySize, SMEM);

    prep_weights_kernel<<<(Cout * KDIM + 255) / 256, 256>>>(w, offset_w, mod_w);
    offmask_kernel<<<NPIX / 128, 128>>>(x, offset_b, mod_b);
    main_kernel<<<NPIX / 64, 256, SMEM>>>(x, bias, out);
}

// round 7
// speedup vs baseline: 2.9033x; 1.1475x over previous
#include <cuda_runtime.h>
#include <math.h>

// Problem constants
#define Bn   8
#define Cin  128
#define Cout 128
#define Hn   112
#define Wn   112
#define Kk   9
#define HW   (Hn*Wn)            // 12544
#define NPIX (Bn*HW)            // 100352
#define KDIM (Cin*Kk)           // 1152

#define CH   4                  // channels per chunk
#define NCH  (Cin/CH)           // 32 chunks
#define KCH  (CH*Kk)            // 36 logical k per chunk
#define KP   40                 // padded k per chunk (5 mma k-steps of 8)
#define KST  40                 // smem row stride (words)

// ---------------- device scratch ----------------
__device__ float4 g_wP4[NCH*Cout*(KP/4)];    // pre-permuted tf32 weights [chunk][o][KP]
__device__ float  g_owT[KDIM*28];            // offset+mask weights, [kk][m]
__device__ float4 g_meta_w[NPIX*Kk];         // bilinear tap weights (mask folded)
__device__ int4   g_meta_off[NPIX*Kk];       // clamped plane offsets y*W+x

static __device__ __forceinline__ float to_tf32(float x) {
    float r;
    asm("cvt.rna.tf32.f32 %0, %1;" : "=f"(r) : "f"(x));
    return r;
}
// storage position of logical k within a chunk row (frag-pair interleave)
static __device__ __forceinline__ int kpos(int kkl) {
    int j = kkl & 7;
    return (kkl >> 3) * 8 + 2 * (j & 3) + (j >> 2);
}

// ---------------- kernel 0: weight prep (permute + tf32 round) ----------------
__global__ void prep_weights_kernel(const float* __restrict__ w,
                                    const float* __restrict__ ow,
                                    const float* __restrict__ mw) {
    int idx = blockIdx.x * 256 + threadIdx.x;
    if (idx < NCH * Cout * KP) {
        int ch = idx / (Cout * KP);
        int r  = idx - ch * (Cout * KP);
        int o  = r / KP;
        int p  = r - o * KP;
        int ks = p >> 3, q = p & 7;
        int j  = (q & 1) * 4 + (q >> 1);      // inverse of kpos
        int kkl = ks * 8 + j;
        float v = 0.f;
        if (kkl < KCH) {
            int c  = ch * CH + kkl / 9;
            int kk = kkl - (kkl / 9) * 9;
            v = to_tf32(w[(size_t)o * KDIM + c * 9 + kk]);
        }
        ((float*)g_wP4)[idx] = v;
    }
    if (idx < KDIM * 28) {
        int kk = idx / 28, m = idx - (idx / 28) * 28;
        float v = 0.f;
        if (m < 18)      v = ow[m * KDIM + kk];
        else if (m < 27) v = mw[(m - 18) * KDIM + kk];
        g_owT[idx] = v;
    }
}

// ---------------- kernel 1: offset/mask conv -> sampling metadata (fp32) ----------------
__global__ void __launch_bounds__(128)
offmask_kernel(const float* __restrict__ x,
               const float* __restrict__ ob,
               const float* __restrict__ mb) {
    __shared__ __align__(16) float s_w[16 * 9 * 28];
    const int tid = threadIdx.x;
    const int pix = blockIdx.x * 128 + tid;
    const int b = pix / HW;
    const int rem = pix - b * HW;
    const int h = rem / Wn;
    const int wc = rem - h * Wn;
    const float* xb = x + (size_t)b * Cin * HW;

    float a[28];
#pragma unroll
    for (int m = 0; m < 28; m++)
        a[m] = (m < 18) ? __ldg(ob + m) : ((m < 27) ? __ldg(mb + m - 18) : 0.f);

    for (int c0 = 0; c0 < Cin; c0 += 16) {
        __syncthreads();
        for (int i = tid; i < 4032; i += 128) s_w[i] = g_owT[c0 * 252 + i];
        __syncthreads();
#pragma unroll 4
        for (int cc = 0; cc < 16; ++cc) {
            const float* xc = xb + (c0 + cc) * HW;
            float tap[9];
#pragma unroll
            for (int di = 0; di < 3; di++)
#pragma unroll
                for (int dj = 0; dj < 3; dj++) {
                    int y = h - 1 + di, xx = wc - 1 + dj;
                    bool ok = ((unsigned)y < (unsigned)Hn) && ((unsigned)xx < (unsigned)Wn);
                    tap[di * 3 + dj] = ok ? __ldg(xc + y * Wn + xx) : 0.f;
                }
#pragma unroll
            for (int k = 0; k < 9; k++) {
                float xv = tap[k];
                const float4* wr = (const float4*)&s_w[(cc * 9 + k) * 28];
#pragma unroll
                for (int q = 0; q < 7; q++) {
                    float4 wv = wr[q];
                    a[q * 4 + 0] += xv * wv.x;
                    a[q * 4 + 1] += xv * wv.y;
                    a[q * 4 + 2] += xv * wv.z;
                    a[q * 4 + 3] += xv * wv.w;
                }
            }
        }
    }

#pragma unroll
    for (int k = 0; k < 9; k++) {
        float dy = a[2 * k], dx = a[2 * k + 1];
        float mraw = a[18 + k];
        float mval = 2.f / (1.f + expf(-mraw));
        int ki = k / 3, kj = k - ki * 3;
        float ys = (float)(h - 1 + ki) + dy;
        float xs = (float)(wc - 1 + kj) + dx;
        float y0f = floorf(ys), x0f = floorf(xs);
        float ly = ys - y0f, lx = xs - x0f;
        int y0 = (int)y0f, x0 = (int)x0f;
        int y1 = y0 + 1, x1 = x0 + 1;
        float vy0 = ((unsigned)y0 < (unsigned)Hn) ? 1.f : 0.f;
        float vy1 = ((unsigned)y1 < (unsigned)Hn) ? 1.f : 0.f;
        float vx0 = ((unsigned)x0 < (unsigned)Wn) ? 1.f : 0.f;
        float vx1 = ((unsigned)x1 < (unsigned)Wn) ? 1.f : 0.f;
        float w00 = mval * (1.f - ly) * (1.f - lx) * vy0 * vx0;
        float w01 = mval * (1.f - ly) * lx          * vy0 * vx1;
        float w10 = mval * ly          * (1.f - lx) * vy1 * vx0;
        float w11 = mval * ly          * lx          * vy1 * vx1;
        int y0c = min(max(y0, 0), Hn - 1), y1c = min(max(y1, 0), Hn - 1);
        int x0c = min(max(x0, 0), Wn - 1), x1c = min(max(x1, 0), Wn - 1);
        int oy0 = y0c * Wn, oy1 = y1c * Wn;
        g_meta_w[pix * 9 + k]   = make_float4(w00, w01, w10, w11);
        g_meta_off[pix * 9 + k] = make_int4(oy0 + x0c, oy0 + x1c, oy1 + x0c, oy1 + x1c);
    }
}

// ---------------- kernel 2: pipelined fused sample + TF32 MMA ----------------
// Block: 256 threads = 8 warps, tile = 64 px (M) x 128 out (N).
// Warp grid 2(M) x 4(N); warp tile 32x32 via 2x4 m16n8k8 tf32 atoms per k-step.
// Double-buffered s_s/s_w; chunk i+1 gathers prefetched to regs during MMA of chunk i.
__global__ void __launch_bounds__(256, 2)
main_kernel(const float* __restrict__ x,
            const float* __restrict__ bias,
            float* __restrict__ out) {
    extern __shared__ char dyn[];
    float4* s_mw = (float4*)dyn;                         //  9216 B
    int4*   s_mo = (int4*)(dyn + 9216);                  //  9216 B
    float*  s_s  = (float*)(dyn + 18432);                // 2 x 64*40*4  = 20480 B
    float*  s_w  = (float*)(dyn + 18432 + 20480);        // 2 x 128*40*4 = 40960 B

    const int tid  = threadIdx.x;
    const int pix0 = blockIdx.x * 64;
    const int b    = pix0 / HW;
    const int hw0  = pix0 - b * HW;

    for (int i = tid; i < 576; i += 256) {
        s_mw[i] = g_meta_w[pix0 * 9 + i];
        s_mo[i] = g_meta_off[pix0 * 9 + i];
    }
    // zero the pad lanes of both s_s buffers (logical k 36..39 -> pos 33,35,37,39)
    for (int i = tid; i < 512; i += 256) {
        int bu = i >> 8, r = i & 255;
        int spz = r >> 2, pj = r & 3;
        s_s[bu * 2560 + spz * KST + 33 + 2 * pj] = 0.f;
    }
    __syncthreads();   // metadata must be visible before ANY thread samples with it

    const int lane = tid & 31;
    const int wid  = tid >> 5;
    const int m0   = (wid & 1) * 32;
    const int n0   = (wid >> 1) * 32;
    const int arow = lane >> 2;
    const int acol = lane & 3;
    const int sp   = tid >> 2;            // pixel 0..63 for sampling
    const int kq   = tid & 3;             // k phase 0..3

    const float* xb = x + (size_t)b * Cin * HW;
    float acc[2][4][4];
#pragma unroll
    for (int ma = 0; ma < 2; ma++)
#pragma unroll
        for (int na = 0; na < 4; na++)
#pragma unroll
            for (int q = 0; q < 4; q++) acc[ma][na][q] = 0.f;

    // ---- prologue: stage chunk 0 into buffer 0 ----
    {
        const float4* wp = g_wP4;         // chunk 0
#pragma unroll
        for (int j = 0; j < 5; j++)
            ((float4*)s_w)[tid + j * 256] = wp[tid + j * 256];
#pragma unroll
        for (int s = 0; s < 9; s++) {
            int kkl = kq + 4 * s;
            int cc = kkl / 9, k = kkl - cc * 9;
            const float* xc = xb + cc * HW;
            int mi = sp * 9 + k;
            float4 wv = s_mw[mi];
            int4  ov = s_mo[mi];
            float v = wv.x * __ldg(xc + ov.x) + wv.y * __ldg(xc + ov.y)
                    + wv.z * __ldg(xc + ov.z) + wv.w * __ldg(xc + ov.w);
            s_s[sp * KST + kpos(kkl)] = to_tf32(v);
        }
    }
    __syncthreads();

    for (int i = 0; i < NCH; i++) {
        const int cur = i & 1, nxt = cur ^ 1;
        const bool pf = (i + 1) < NCH;

        // ---- 1. prefetch chunk i+1 into registers (LDGs issue early) ----
        float4 wreg[5];
        float g0[9], g1[9], g2[9], g3[9];
        if (pf) {
            const float4* wp = g_wP4 + (size_t)(i + 1) * (Cout * KP / 4);
#pragma unroll
            for (int j = 0; j < 5; j++) wreg[j] = __ldg(wp + tid + j * 256);
            const int c0n = (i + 1) * CH;
#pragma unroll
            for (int s = 0; s < 9; s++) {
                int kkl = kq + 4 * s;
                int cc = kkl / 9, k = kkl - cc * 9;
                const float* xc = xb + (c0n + cc) * HW;
                int4 ov = s_mo[sp * 9 + k];
                g0[s] = __ldg(xc + ov.x);
                g1[s] = __ldg(xc + ov.y);
                g2[s] = __ldg(xc + ov.z);
                g3[s] = __ldg(xc + ov.w);
            }
        }

        // ---- 2. MMA on chunk i ----
        {
            const float* ss = s_s + cur * 2560;
            const float* sw = s_w + cur * 5120;
#pragma unroll
            for (int ks = 0; ks < 5; ks++) {
                const int ko = ks * 8 + 2 * acol;
                unsigned a[2][4];
#pragma unroll
                for (int ma = 0; ma < 2; ma++) {
                    const int base = (m0 + ma * 16 + arow) * KST + ko;
                    uint2 lo = *(const uint2*)(ss + base);            // a0,a2
                    uint2 hi = *(const uint2*)(ss + base + 8 * KST);  // a1,a3
                    a[ma][0] = lo.x; a[ma][1] = hi.x;
                    a[ma][2] = lo.y; a[ma][3] = hi.y;
                }
#pragma unroll
                for (int na = 0; na < 4; na++) {
                    uint2 bb = *(const uint2*)(sw + (n0 + na * 8 + arow) * KST + ko);
#pragma unroll
                    for (int ma = 0; ma < 2; ma++) {
                        asm volatile(
                            "mma.sync.aligned.m16n8k8.row.col.f32.tf32.tf32.f32 "
                            "{%0,%1,%2,%3}, {%4,%5,%6,%7}, {%8,%9}, {%0,%1,%2,%3};"
                            : "+f"(acc[ma][na][0]), "+f"(acc[ma][na][1]),
                              "+f"(acc[ma][na][2]), "+f"(acc[ma][na][3])
                            : "r"(a[ma][0]), "r"(a[ma][1]), "r"(a[ma][2]), "r"(a[ma][3]),
                              "r"(bb.x), "r"(bb.y));
                    }
                }
            }
        }

        // ---- 3. writeback chunk i+1 into buffer nxt ----
        if (pf) {
            float4* swn = (float4*)(s_w + nxt * 5120);
#pragma unroll
            for (int j = 0; j < 5; j++) swn[tid + j * 256] = wreg[j];
            float* ssn = s_s + nxt * 2560;
#pragma unroll
            for (int s = 0; s < 9; s++) {
                int kkl = kq + 4 * s;
                int cc = kkl / 9, k = kkl - cc * 9;
                float4 wv = s_mw[sp * 9 + k];
                float v = wv.x * g0[s] + wv.y * g1[s] + wv.z * g2[s] + wv.w * g3[s];
                ssn[sp * KST + kpos(kkl)] = to_tf32(v);
            }
        }
        __syncthreads();
    }

    // ---- epilogue: fp32 bias add + stores ----
#pragma unroll
    for (int ma = 0; ma < 2; ma++) {
        int prow = hw0 + m0 + ma * 16 + arow;
#pragma unroll
        for (int na = 0; na < 4; na++) {
            int o = n0 + na * 8 + 2 * acol;
            float b0 = __ldg(bias + o);
            float b1 = __ldg(bias + o + 1);
            float* p0 = out + ((size_t)b * Cout + o) * HW + prow;
            float* p1 = p0 + HW;
            p0[0] = acc[ma][na][0] + b0;
            p1[0] = acc[ma][na][1] + b1;
            p0[8] = acc[ma][na][2] + b0;
            p1[8] = acc[ma][na][3] + b1;
        }
    }
}

// ---------------- launcher ----------------
extern "C" void kernel_launch(void* const* d_in, const int* in_sizes, int n_in,
                              void* d_out, int out_size) {
    const float* x        = (const float*)d_in[0];
    const float* offset_w = (const float*)d_in[1];
    const float* offset_b = (const float*)d_in[2];
    const float* mod_w    = (const float*)d_in[3];
    const float* mod_b    = (const float*)d_in[4];
    const float* w        = (const float*)d_in[5];
    const float* bias     = (const float*)d_in[6];
    float* out = (float*)d_out;

    const int SMEM = 9216 + 9216 + 20480 + 40960;   // 79872 B
    cudaFuncSetAttribute(main_kernel, cudaFuncAttributeMaxDynamicSharedMemorySize, SMEM);

    prep_weights_kernel<<<(NCH * Cout * KP + 255) / 256, 256>>>(w, offset_w, mod_w);
    offmask_kernel<<<NPIX / 128, 128>>>(x, offset_b, mod_b);
    main_kernel<<<NPIX / 64, 256, SMEM>>>(x, bias, out);
}

// round 8
// speedup vs baseline: 2.9454x; 1.0145x over previous
#include <cuda_runtime.h>
#include <math.h>

// Problem constants
#define Bn   8
#define Cin  128
#define Cout 128
#define Hn   112
#define Wn   112
#define Kk   9
#define HW   (Hn*Wn)            // 12544
#define NPIX (Bn*HW)            // 100352
#define KDIM (Cin*Kk)           // 1152

#define CH   4                  // main: channels per chunk
#define NCH  (Cin/CH)           // 32 chunks
#define KCH  (CH*Kk)            // 36 logical k per chunk
#define KP   40                 // main: padded k per chunk
#define KST  40                 // main: smem row stride (words)

#define OCH   8                 // offmask: channels per chunk
#define ONCH  (Cin/OCH)         // 16 chunks
#define OKP   72                // offmask: k per chunk (8*9, = 9 k-steps exactly)

// ---------------- device scratch ----------------
__device__ float4 g_wP4[NCH*Cout*(KP/4)];      // main weights, permuted tf32
__device__ float4 g_owP4[ONCH*32*(OKP/4)];     // offmask weights [chunk][n=32][72], permuted tf32
__device__ float4 g_meta_w[NPIX*Kk];           // bilinear tap weights (mask folded)
__device__ int4   g_meta_off[NPIX*Kk];         // clamped plane offsets y*W+x

static __device__ __forceinline__ float to_tf32(float x) {
    float r;
    asm("cvt.rna.tf32.f32 %0, %1;" : "=f"(r) : "f"(x));
    return r;
}
// storage position of logical k within an 8-wide k-step (frag-pair interleave)
static __device__ __forceinline__ int kpos(int kkl) {
    int j = kkl & 7;
    return (kkl >> 3) * 8 + 2 * (j & 3) + (j >> 2);
}

// ---------------- kernel 0: weight prep (permute + tf32 round) ----------------
__global__ void prep_weights_kernel(const float* __restrict__ w,
                                    const float* __restrict__ ow,
                                    const float* __restrict__ mw) {
    int idx = blockIdx.x * 256 + threadIdx.x;
    if (idx < NCH * Cout * KP) {
        int ch = idx / (Cout * KP);
        int r  = idx - ch * (Cout * KP);
        int o  = r / KP;
        int p  = r - o * KP;
        int ks = p >> 3, q = p & 7;
        int j  = (q & 1) * 4 + (q >> 1);      // inverse of kpos
        int kkl = ks * 8 + j;
        float v = 0.f;
        if (kkl < KCH) {
            int c  = ch * CH + kkl / 9;
            int kk = kkl - (kkl / 9) * 9;
            v = to_tf32(w[(size_t)o * KDIM + c * 9 + kk]);
        }
        ((float*)g_wP4)[idx] = v;
    }
    if (idx < ONCH * 32 * OKP) {              // 36864
        int ch = idx / (32 * OKP);
        int r  = idx - ch * (32 * OKP);
        int n  = r / OKP;
        int p  = r - n * OKP;
        int ks = p >> 3, q = p & 7;
        int j  = (q & 1) * 4 + (q >> 1);
        int kkl = ks * 8 + j;                 // 0..71
        int c   = ch * OCH + kkl / 9;
        int kk  = kkl - (kkl / 9) * 9;
        int gk  = c * 9 + kk;
        float v = 0.f;
        if (n < 18)      v = to_tf32(ow[(size_t)n * KDIM + gk]);
        else if (n < 27) v = to_tf32(mw[(size_t)(n - 18) * KDIM + gk]);
        ((float*)g_owP4)[idx] = v;
    }
}

// ---------------- kernel 1: offmask conv via TF32 MMA -> sampling metadata ----------------
// Block: 256 threads = 8 warps; tile 64 px (M) x 32 out (N, 28 used), K=1152 in 16 chunks of 72.
// Warp grid 4(M) x 2(N): warp tile 16x16, 1x2 m16n8k8 atoms per k-step.
__global__ void __launch_bounds__(256)
offmask_kernel(const float* __restrict__ x,
               const float* __restrict__ ob,
               const float* __restrict__ mb) {
    __shared__ __align__(16) float s_x[64 * OKP];    // 18432 B
    __shared__ __align__(16) float s_ww[32 * OKP];   //  9216 B
    __shared__ float s_r[64 * 32];                   //  8192 B

    const int tid  = threadIdx.x;
    const int pix0 = blockIdx.x * 64;
    const int b    = pix0 / HW;
    const float* xb = x + (size_t)b * Cin * HW;

    const int lane = tid & 31;
    const int wid  = tid >> 5;
    const int m0   = (wid & 3) * 16;
    const int n0   = (wid >> 2) * 16;
    const int arow = lane >> 2;
    const int acol = lane & 3;
    const int sp   = tid >> 2;              // pixel 0..63
    const int kq   = tid & 3;               // tap phase

    // per-pixel coords for staging
    const int pixS = pix0 + sp;
    const int remS = pixS - b * HW;
    const int hS   = remS / Wn;
    const int wS   = remS - hS * Wn;

    float acc[2][4];
#pragma unroll
    for (int na = 0; na < 2; na++)
#pragma unroll
        for (int q = 0; q < 4; q++) acc[na][q] = 0.f;

    for (int ch = 0; ch < ONCH; ch++) {
        // ---- stage weights (576 float4) ----
        const float4* wp = g_owP4 + ch * 576;
        for (int i = tid; i < 576; i += 256)
            ((float4*)s_ww)[i] = __ldg(wp + i);

        // ---- stage taps: 18 per thread ----
#pragma unroll
        for (int s = 0; s < 18; s++) {
            int kkl = kq + 4 * s;
            int cc = kkl / 9, tk = kkl - cc * 9;
            int di = tk / 3, dj = tk - di * 3;
            int y = hS - 1 + di, xx = wS - 1 + dj;
            bool ok = ((unsigned)y < (unsigned)Hn) && ((unsigned)xx < (unsigned)Wn);
            float v = ok ? __ldg(xb + (size_t)(ch * OCH + cc) * HW + y * Wn + xx) : 0.f;
            s_x[sp * OKP + kpos(kkl)] = to_tf32(v);
        }
        __syncthreads();

        // ---- 9 k-steps of MMA ----
#pragma unroll
        for (int ks = 0; ks < 9; ks++) {
            const int ko = ks * 8 + 2 * acol;
            const int abase = (m0 + arow) * OKP + ko;
            uint2 lo = *(const uint2*)(s_x + abase);
            uint2 hi = *(const uint2*)(s_x + abase + 8 * OKP);
#pragma unroll
            for (int na = 0; na < 2; na++) {
                uint2 bb = *(const uint2*)(s_ww + (n0 + na * 8 + arow) * OKP + ko);
                asm volatile(
                    "mma.sync.aligned.m16n8k8.row.col.f32.tf32.tf32.f32 "
                    "{%0,%1,%2,%3}, {%4,%5,%6,%7}, {%8,%9}, {%0,%1,%2,%3};"
                    : "+f"(acc[na][0]), "+f"(acc[na][1]),
                      "+f"(acc[na][2]), "+f"(acc[na][3])
                    : "r"(lo.x), "r"(hi.x), "r"(lo.y), "r"(hi.y),
                      "r"(bb.x), "r"(bb.y));
            }
        }
        __syncthreads();
    }

    // ---- dump accumulators to smem ----
#pragma unroll
    for (int na = 0; na < 2; na++) {
        int col = n0 + na * 8 + 2 * acol;
        int r0 = m0 + arow, r1 = r0 + 8;
        s_r[r0 * 32 + col]     = acc[na][0];
        s_r[r0 * 32 + col + 1] = acc[na][1];
        s_r[r1 * 32 + col]     = acc[na][2];
        s_r[r1 * 32 + col + 1] = acc[na][3];
    }
    __syncthreads();

    // ---- metadata epilogue (fp32): 4 threads per pixel, taps ph, ph+4, ph+8 ----
    const int px = tid >> 2;
    const int ph = tid & 3;
    const int pix = pix0 + px;
    const int rem = pix - b * HW;
    const int h  = rem / Wn;
    const int wc = rem - h * Wn;
    const float* rr = s_r + px * 32;

#pragma unroll
    for (int t = 0; t < 3; t++) {
        int k = ph + 4 * t;
        if (k >= 9) break;
        float dy = rr[2 * k]     + __ldg(ob + 2 * k);
        float dx = rr[2 * k + 1] + __ldg(ob + 2 * k + 1);
        float mraw = rr[18 + k]  + __ldg(mb + k);
        float mval = 2.f / (1.f + expf(-mraw));
        int ki = k / 3, kj = k - ki * 3;
        float ys = (float)(h - 1 + ki) + dy;
        float xs = (float)(wc - 1 + kj) + dx;
        float y0f = floorf(ys), x0f = floorf(xs);
        float ly = ys - y0f, lx = xs - x0f;
        int y0 = (int)y0f, x0 = (int)x0f;
        int y1 = y0 + 1, x1 = x0 + 1;
        float vy0 = ((unsigned)y0 < (unsigned)Hn) ? 1.f : 0.f;
        float vy1 = ((unsigned)y1 < (unsigned)Hn) ? 1.f : 0.f;
        float vx0 = ((unsigned)x0 < (unsigned)Wn) ? 1.f : 0.f;
        float vx1 = ((unsigned)x1 < (unsigned)Wn) ? 1.f : 0.f;
        float w00 = mval * (1.f - ly) * (1.f - lx) * vy0 * vx0;
        float w01 = mval * (1.f - ly) * lx          * vy0 * vx1;
        float w10 = mval * ly          * (1.f - lx) * vy1 * vx0;
        float w11 = mval * ly          * lx          * vy1 * vx1;
        int y0c = min(max(y0, 0), Hn - 1), y1c = min(max(y1, 0), Hn - 1);
        int x0c = min(max(x0, 0), Wn - 1), x1c = min(max(x1, 0), Wn - 1);
        int oy0 = y0c * Wn, oy1 = y1c * Wn;
        g_meta_w[pix * 9 + k]   = make_float4(w00, w01, w10, w11);
        g_meta_off[pix * 9 + k] = make_int4(oy0 + x0c, oy0 + x1c, oy1 + x0c, oy1 + x1c);
    }
}

// ---------------- kernel 2: pipelined fused sample + TF32 MMA (unchanged R7) ----------------
__global__ void __launch_bounds__(256, 2)
main_kernel(const float* __restrict__ x,
            const float* __restrict__ bias,
            float* __restrict__ out) {
    extern __shared__ char dyn[];
    float4* s_mw = (float4*)dyn;                         //  9216 B
    int4*   s_mo = (int4*)(dyn + 9216);                  //  9216 B
    float*  s_s  = (float*)(dyn + 18432);                // 2 x 64*40*4  = 20480 B
    float*  s_w  = (float*)(dyn + 18432 + 20480);        // 2 x 128*40*4 = 40960 B

    const int tid  = threadIdx.x;
    const int pix0 = blockIdx.x * 64;
    const int b    = pix0 / HW;
    const int hw0  = pix0 - b * HW;

    for (int i = tid; i < 576; i += 256) {
        s_mw[i] = g_meta_w[pix0 * 9 + i];
        s_mo[i] = g_meta_off[pix0 * 9 + i];
    }
    for (int i = tid; i < 512; i += 256) {
        int bu = i >> 8, r = i & 255;
        int spz = r >> 2, pj = r & 3;
        s_s[bu * 2560 + spz * KST + 33 + 2 * pj] = 0.f;
    }
    __syncthreads();

    const int lane = tid & 31;
    const int wid  = tid >> 5;
    const int m0   = (wid & 1) * 32;
    const int n0   = (wid >> 1) * 32;
    const int arow = lane >> 2;
    const int acol = lane & 3;
    const int sp   = tid >> 2;
    const int kq   = tid & 3;

    const float* xb = x + (size_t)b * Cin * HW;
    float acc[2][4][4];
#pragma unroll
    for (int ma = 0; ma < 2; ma++)
#pragma unroll
        for (int na = 0; na < 4; na++)
#pragma unroll
            for (int q = 0; q < 4; q++) acc[ma][na][q] = 0.f;

    {
        const float4* wp = g_wP4;
#pragma unroll
        for (int j = 0; j < 5; j++)
            ((float4*)s_w)[tid + j * 256] = wp[tid + j * 256];
#pragma unroll
        for (int s = 0; s < 9; s++) {
            int kkl = kq + 4 * s;
            int cc = kkl / 9, k = kkl - cc * 9;
            const float* xc = xb + cc * HW;
            int mi = sp * 9 + k;
            float4 wv = s_mw[mi];
            int4  ov = s_mo[mi];
            float v = wv.x * __ldg(xc + ov.x) + wv.y * __ldg(xc + ov.y)
                    + wv.z * __ldg(xc + ov.z) + wv.w * __ldg(xc + ov.w);
            s_s[sp * KST + kpos(kkl)] = to_tf32(v);
        }
    }
    __syncthreads();

    for (int i = 0; i < NCH; i++) {
        const int cur = i & 1, nxt = cur ^ 1;
        const bool pf = (i + 1) < NCH;

        float4 wreg[5];
        float g0[9], g1[9], g2[9], g3[9];
        if (pf) {
            const float4* wp = g_wP4 + (size_t)(i + 1) * (Cout * KP / 4);
#pragma unroll
            for (int j = 0; j < 5; j++) wreg[j] = __ldg(wp + tid + j * 256);
            const int c0n = (i + 1) * CH;
#pragma unroll
            for (int s = 0; s < 9; s++) {
                int kkl = kq + 4 * s;
                int cc = kkl / 9, k = kkl - cc * 9;
                const float* xc = xb + (c0n + cc) * HW;
                int4 ov = s_mo[sp * 9 + k];
                g0[s] = __ldg(xc + ov.x);
                g1[s] = __ldg(xc + ov.y);
                g2[s] = __ldg(xc + ov.z);
                g3[s] = __ldg(xc + ov.w);
            }
        }

        {
            const float* ss = s_s + cur * 2560;
            const float* sw = s_w + cur * 5120;
#pragma unroll
            for (int ks = 0; ks < 5; ks++) {
                const int ko = ks * 8 + 2 * acol;
                unsigned a[2][4];
#pragma unroll
                for (int ma = 0; ma < 2; ma++) {
                    const int base = (m0 + ma * 16 + arow) * KST + ko;
                    uint2 lo = *(const uint2*)(ss + base);
                    uint2 hi = *(const uint2*)(ss + base + 8 * KST);
                    a[ma][0] = lo.x; a[ma][1] = hi.x;
                    a[ma][2] = lo.y; a[ma][3] = hi.y;
                }
#pragma unroll
                for (int na = 0; na < 4; na++) {
                    uint2 bb = *(const uint2*)(sw + (n0 + na * 8 + arow) * KST + ko);
#pragma unroll
                    for (int ma = 0; ma < 2; ma++) {
                        asm volatile(
                            "mma.sync.aligned.m16n8k8.row.col.f32.tf32.tf32.f32 "
                            "{%0,%1,%2,%3}, {%4,%5,%6,%7}, {%8,%9}, {%0,%1,%2,%3};"
                            : "+f"(acc[ma][na][0]), "+f"(acc[ma][na][1]),
                              "+f"(acc[ma][na][2]), "+f"(acc[ma][na][3])
                            : "r"(a[ma][0]), "r"(a[ma][1]), "r"(a[ma][2]), "r"(a[ma][3]),
                              "r"(bb.x), "r"(bb.y));
                    }
                }
            }
        }

        if (pf) {
            float4* swn = (float4*)(s_w + nxt * 5120);
#pragma unroll
            for (int j = 0; j < 5; j++) swn[tid + j * 256] = wreg[j];
            float* ssn = s_s + nxt * 2560;
#pragma unroll
            for (int s = 0; s < 9; s++) {
                int kkl = kq + 4 * s;
                int cc = kkl / 9, k = kkl - cc * 9;
                float4 wv = s_mw[sp * 9 + k];
                float v = wv.x * g0[s] + wv.y * g1[s] + wv.z * g2[s] + wv.w * g3[s];
                ssn[sp * KST + kpos(kkl)] = to_tf32(v);
            }
        }
        __syncthreads();
    }

#pragma unroll
    for (int ma = 0; ma < 2; ma++) {
        int prow = hw0 + m0 + ma * 16 + arow;
#pragma unroll
        for (int na = 0; na < 4; na++) {
            int o = n0 + na * 8 + 2 * acol;
            float b0 = __ldg(bias + o);
            float b1 = __ldg(bias + o + 1);
            float* p0 = out + ((size_t)b * Cout + o) * HW + prow;
            float* p1 = p0 + HW;
            p0[0] = acc[ma][na][0] + b0;
            p1[0] = acc[ma][na][1] + b1;
            p0[8] = acc[ma][na][2] + b0;
            p1[8] = acc[ma][na][3] + b1;
        }
    }
}

// ---------------- launcher ----------------
extern "C" void kernel_launch(void* const* d_in, const int* in_sizes, int n_in,
                              void* d_out, int out_size) {
    const float* x        = (const float*)d_in[0];
    const float* offset_w = (const float*)d_in[1];
    const float* offset_b = (const float*)d_in[2];
    const float* mod_w    = (const float*)d_in[3];
    const float* mod_b    = (const float*)d_in[4];
    const float* w        = (const float*)d_in[5];
    const float* bias     = (const float*)d_in[6];
    float* out = (float*)d_out;

    const int SMEM = 9216 + 9216 + 20480 + 40960;   // 79872 B
    cudaFuncSetAttribute(main_kernel, cudaFuncAttributeMaxDynamicSharedMemorySize, SMEM);

    prep_weights_kernel<<<(NCH * Cout * KP + 255) / 256, 256>>>(w, offset_w, mod_w);
    offmask_kernel<<<NPIX / 64, 256>>>(x, offset_b, mod_b);
    main_kernel<<<NPIX / 64, 256, SMEM>>>(x, bias, out);
}

// round 9
// speedup vs baseline: 2.9600x; 1.0050x over previous
#include <cuda_runtime.h>
#include <math.h>

// Problem constants
#define Bn   8
#define Cin  128
#define Cout 128
#define Hn   112
#define Wn   112
#define Kk   9
#define HW   (Hn*Wn)            // 12544
#define NPIX (Bn*HW)            // 100352
#define KDIM (Cin*Kk)           // 1152

#define CH   4                  // main: channels per chunk
#define NCH  (Cin/CH)           // 32 chunks
#define KCH  (CH*Kk)            // 36 logical k per chunk
#define KP   40                 // main: padded k per chunk
#define KST  40                 // main: smem row stride (words)

#define OCH   8                 // offmask: channels per chunk
#define ONCH  (Cin/OCH)         // 16 chunks
#define OKP   72                // offmask: k per chunk (8*9, = 9 k-steps exactly)

// ---------------- device scratch ----------------
__device__ float4 g_wP4[NCH*Cout*(KP/4)];      // main weights, permuted tf32
__device__ float4 g_owP4[ONCH*32*(OKP/4)];     // offmask weights [chunk][n=32][72], permuted tf32
__device__ float4 g_meta_w[NPIX*Kk];           // bilinear tap weights (mask folded)
__device__ int4   g_meta_off[NPIX*Kk];         // clamped plane offsets y*W+x

static __device__ __forceinline__ float to_tf32(float x) {
    float r;
    asm("cvt.rna.tf32.f32 %0, %1;" : "=f"(r) : "f"(x));
    return r;
}
// storage position of logical k within an 8-wide k-step (frag-pair interleave)
static __device__ __forceinline__ int kpos(int kkl) {
    int j = kkl & 7;
    return (kkl >> 3) * 8 + 2 * (j & 3) + (j >> 2);
}

// ---------------- kernel 0: weight prep (permute + tf32 round) ----------------
__global__ void prep_weights_kernel(const float* __restrict__ w,
                                    const float* __restrict__ ow,
                                    const float* __restrict__ mw) {
    int idx = blockIdx.x * 256 + threadIdx.x;
    if (idx < NCH * Cout * KP) {
        int ch = idx / (Cout * KP);
        int r  = idx - ch * (Cout * KP);
        int o  = r / KP;
        int p  = r - o * KP;
        int ks = p >> 3, q = p & 7;
        int j  = (q & 1) * 4 + (q >> 1);      // inverse of kpos
        int kkl = ks * 8 + j;
        float v = 0.f;
        if (kkl < KCH) {
            int c  = ch * CH + kkl / 9;
            int kk = kkl - (kkl / 9) * 9;
            v = to_tf32(w[(size_t)o * KDIM + c * 9 + kk]);
        }
        ((float*)g_wP4)[idx] = v;
    }
    if (idx < ONCH * 32 * OKP) {              // 36864
        int ch = idx / (32 * OKP);
        int r  = idx - ch * (32 * OKP);
        int n  = r / OKP;
        int p  = r - n * OKP;
        int ks = p >> 3, q = p & 7;
        int j  = (q & 1) * 4 + (q >> 1);
        int kkl = ks * 8 + j;                 // 0..71
        int c   = ch * OCH + kkl / 9;
        int kk  = kkl - (kkl / 9) * 9;
        int gk  = c * 9 + kk;
        float v = 0.f;
        if (n < 18)      v = to_tf32(ow[(size_t)n * KDIM + gk]);
        else if (n < 27) v = to_tf32(mw[(size_t)(n - 18) * KDIM + gk]);
        ((float*)g_owP4)[idx] = v;
    }
}

// ---------------- kernel 1: offmask conv via TF32 MMA -> sampling metadata ----------------
// Block: 256 threads = 8 warps; tile 64 px (M) x 32 out (N, 28 used), K=1152 in 16 chunks of 72.
// Warp grid 4(M) x 2(N): warp tile 16x16, 1x2 m16n8k8 atoms per k-step.
__global__ void __launch_bounds__(256)
offmask_kernel(const float* __restrict__ x,
               const float* __restrict__ ob,
               const float* __restrict__ mb) {
    __shared__ __align__(16) float s_x[64 * OKP];    // 18432 B
    __shared__ __align__(16) float s_ww[32 * OKP];   //  9216 B
    __shared__ float s_r[64 * 32];                   //  8192 B

    const int tid  = threadIdx.x;
    const int pix0 = blockIdx.x * 64;
    const int b    = pix0 / HW;
    const float* xb = x + (size_t)b * Cin * HW;

    const int lane = tid & 31;
    const int wid  = tid >> 5;
    const int m0   = (wid & 3) * 16;
    const int n0   = (wid >> 2) * 16;
    const int arow = lane >> 2;
    const int acol = lane & 3;
    const int sp   = tid >> 2;              // pixel 0..63
    const int kq   = tid & 3;               // tap phase

    // per-pixel coords for staging
    const int pixS = pix0 + sp;
    const int remS = pixS - b * HW;
    const int hS   = remS / Wn;
    const int wS   = remS - hS * Wn;

    float acc[2][4];
#pragma unroll
    for (int na = 0; na < 2; na++)
#pragma unroll
        for (int q = 0; q < 4; q++) acc[na][q] = 0.f;

    for (int ch = 0; ch < ONCH; ch++) {
        // ---- stage weights (576 float4) ----
        const float4* wp = g_owP4 + ch * 576;
        for (int i = tid; i < 576; i += 256)
            ((float4*)s_ww)[i] = __ldg(wp + i);

        // ---- stage taps: 18 per thread ----
#pragma unroll
        for (int s = 0; s < 18; s++) {
            int kkl = kq + 4 * s;
            int cc = kkl / 9, tk = kkl - cc * 9;
            int di = tk / 3, dj = tk - di * 3;
            int y = hS - 1 + di, xx = wS - 1 + dj;
            bool ok = ((unsigned)y < (unsigned)Hn) && ((unsigned)xx < (unsigned)Wn);
            float v = ok ? __ldg(xb + (size_t)(ch * OCH + cc) * HW + y * Wn + xx) : 0.f;
            s_x[sp * OKP + kpos(kkl)] = to_tf32(v);
        }
        __syncthreads();

        // ---- 9 k-steps of MMA ----
#pragma unroll
        for (int ks = 0; ks < 9; ks++) {
            const int ko = ks * 8 + 2 * acol;
            const int abase = (m0 + arow) * OKP + ko;
            uint2 lo = *(const uint2*)(s_x + abase);
            uint2 hi = *(const uint2*)(s_x + abase + 8 * OKP);
#pragma unroll
            for (int na = 0; na < 2; na++) {
                uint2 bb = *(const uint2*)(s_ww + (n0 + na * 8 + arow) * OKP + ko);
                asm volatile(
                    "mma.sync.aligned.m16n8k8.row.col.f32.tf32.tf32.f32 "
                    "{%0,%1,%2,%3}, {%4,%5,%6,%7}, {%8,%9}, {%0,%1,%2,%3};"
                    : "+f"(acc[na][0]), "+f"(acc[na][1]),
                      "+f"(acc[na][2]), "+f"(acc[na][3])
                    : "r"(lo.x), "r"(hi.x), "r"(lo.y), "r"(hi.y),
                      "r"(bb.x), "r"(bb.y));
            }
        }
        __syncthreads();
    }

    // ---- dump accumulators to smem ----
#pragma unroll
    for (int na = 0; na < 2; na++) {
        int col = n0 + na * 8 + 2 * acol;
        int r0 = m0 + arow, r1 = r0 + 8;
        s_r[r0 * 32 + col]     = acc[na][0];
        s_r[r0 * 32 + col + 1] = acc[na][1];
        s_r[r1 * 32 + col]     = acc[na][2];
        s_r[r1 * 32 + col + 1] = acc[na][3];
    }
    __syncthreads();

    // ---- metadata epilogue (fp32): 4 threads per pixel, taps ph, ph+4, ph+8 ----
    const int px = tid >> 2;
    const int ph = tid & 3;
    const int pix = pix0 + px;
    const int rem = pix - b * HW;
    const int h  = rem / Wn;
    const int wc = rem - h * Wn;
    const float* rr = s_r + px * 32;

#pragma unroll
    for (int t = 0; t < 3; t++) {
        int k = ph + 4 * t;
        if (k >= 9) break;
        float dy = rr[2 * k]     + __ldg(ob + 2 * k);
        float dx = rr[2 * k + 1] + __ldg(ob + 2 * k + 1);
        float mraw = rr[18 + k]  + __ldg(mb + k);
        float mval = 2.f / (1.f + expf(-mraw));
        int ki = k / 3, kj = k - ki * 3;
        float ys = (float)(h - 1 + ki) + dy;
        float xs = (float)(wc - 1 + kj) + dx;
        float y0f = floorf(ys), x0f = floorf(xs);
        float ly = ys - y0f, lx = xs - x0f;
        int y0 = (int)y0f, x0 = (int)x0f;
        int y1 = y0 + 1, x1 = x0 + 1;
        float vy0 = ((unsigned)y0 < (unsigned)Hn) ? 1.f : 0.f;
        float vy1 = ((unsigned)y1 < (unsigned)Hn) ? 1.f : 0.f;
        float vx0 = ((unsigned)x0 < (unsigned)Wn) ? 1.f : 0.f;
        float vx1 = ((unsigned)x1 < (unsigned)Wn) ? 1.f : 0.f;
        float w00 = mval * (1.f - ly) * (1.f - lx) * vy0 * vx0;
        float w01 = mval * (1.f - ly) * lx          * vy0 * vx1;
        float w10 = mval * ly          * (1.f - lx) * vy1 * vx0;
        float w11 = mval * ly          * lx          * vy1 * vx1;
        int y0c = min(max(y0, 0), Hn - 1), y1c = min(max(y1, 0), Hn - 1);
        int x0c = min(max(x0, 0), Wn - 1), x1c = min(max(x1, 0), Wn - 1);
        int oy0 = y0c * Wn, oy1 = y1c * Wn;
        g_meta_w[pix * 9 + k]   = make_float4(w00, w01, w10, w11);
        g_meta_off[pix * 9 + k] = make_int4(oy0 + x0c, oy0 + x1c, oy1 + x0c, oy1 + x1c);
    }
}

// ---------------- kernel 2: pipelined fused sample + TF32 MMA (unchanged R7) ----------------
__global__ void __launch_bounds__(256, 2)
main_kernel(const float* __restrict__ x,
            const float* __restrict__ bias,
            float* __restrict__ out) {
    extern __shared__ char dyn[];
    float4* s_mw = (float4*)dyn;                         //  9216 B
    int4*   s_mo = (int4*)(dyn + 9216);                  //  9216 B
    float*  s_s  = (float*)(dyn + 18432);                // 2 x 64*40*4  = 20480 B
    float*  s_w  = (float*)(dyn + 18432 + 20480);        // 2 x 128*40*4 = 40960 B

    const int tid  = threadIdx.x;
    const int pix0 = blockIdx.x * 64;
    const int b    = pix0 / HW;
    const int hw0  = pix0 - b * HW;

    for (int i = tid; i < 576; i += 256) {
        s_mw[i] = g_meta_w[pix0 * 9 + i];
        s_mo[i] = g_meta_off[pix0 * 9 + i];
    }
    for (int i = tid; i < 512; i += 256) {
        int bu = i >> 8, r = i & 255;
        int spz = r >> 2, pj = r & 3;
        s_s[bu * 2560 + spz * KST + 33 + 2 * pj] = 0.f;
    }
    __syncthreads();

    const int lane = tid & 31;
    const int wid  = tid >> 5;
    const int m0   = (wid & 1) * 32;
    const int n0   = (wid >> 1) * 32;
    const int arow = lane >> 2;
    const int acol = lane & 3;
    const int sp   = tid >> 2;
    const int kq   = tid & 3;

    const float* xb = x + (size_t)b * Cin * HW;
    float acc[2][4][4];
#pragma unroll
    for (int ma = 0; ma < 2; ma++)
#pragma unroll
        for (int na = 0; na < 4; na++)
#pragma unroll
            for (int q = 0; q < 4; q++) acc[ma][na][q] = 0.f;

    {
        const float4* wp = g_wP4;
#pragma unroll
        for (int j = 0; j < 5; j++)
            ((float4*)s_w)[tid + j * 256] = wp[tid + j * 256];
#pragma unroll
        for (int s = 0; s < 9; s++) {
            int kkl = kq + 4 * s;
            int cc = kkl / 9, k = kkl - cc * 9;
            const float* xc = xb + cc * HW;
            int mi = sp * 9 + k;
            float4 wv = s_mw[mi];
            int4  ov = s_mo[mi];
            float v = wv.x * __ldg(xc + ov.x) + wv.y * __ldg(xc + ov.y)
                    + wv.z * __ldg(xc + ov.z) + wv.w * __ldg(xc + ov.w);
            s_s[sp * KST + kpos(kkl)] = to_tf32(v);
        }
    }
    __syncthreads();

    for (int i = 0; i < NCH; i++) {
        const int cur = i & 1, nxt = cur ^ 1;
        const bool pf = (i + 1) < NCH;

        float4 wreg[5];
        float g0[9], g1[9], g2[9], g3[9];
        if (pf) {
            const float4* wp = g_wP4 + (size_t)(i + 1) * (Cout * KP / 4);
#pragma unroll
            for (int j = 0; j < 5; j++) wreg[j] = __ldg(wp + tid + j * 256);
            const int c0n = (i + 1) * CH;
#pragma unroll
            for (int s = 0; s < 9; s++) {
                int kkl = kq + 4 * s;
                int cc = kkl / 9, k = kkl - cc * 9;
                const float* xc = xb + (c0n + cc) * HW;
                int4 ov = s_mo[sp * 9 + k];
                g0[s] = __ldg(xc + ov.x);
                g1[s] = __ldg(xc + ov.y);
                g2[s] = __ldg(xc + ov.z);
                g3[s] = __ldg(xc + ov.w);
            }
        }

        {
            const float* ss = s_s + cur * 2560;
            const float* sw = s_w + cur * 5120;
#pragma unroll
            for (int ks = 0; ks < 5; ks++) {
                const int ko = ks * 8 + 2 * acol;
                unsigned a[2][4];
#pragma unroll
                for (int ma = 0; ma < 2; ma++) {
                    const int base = (m0 + ma * 16 + arow) * KST + ko;
                    uint2 lo = *(const uint2*)(ss + base);
                    uint2 hi = *(const uint2*)(ss + base + 8 * KST);
                    a[ma][0] = lo.x; a[ma][1] = hi.x;
                    a[ma][2] = lo.y; a[ma][3] = hi.y;
                }
#pragma unroll
                for (int na = 0; na < 4; na++) {
                    uint2 bb = *(const uint2*)(sw + (n0 + na * 8 + arow) * KST + ko);
#pragma unroll
                    for (int ma = 0; ma < 2; ma++) {
                        asm volatile(
                            "mma.sync.aligned.m16n8k8.row.col.f32.tf32.tf32.f32 "
                            "{%0,%1,%2,%3}, {%4,%5,%6,%7}, {%8,%9}, {%0,%1,%2,%3};"
                            : "+f"(acc[ma][na][0]), "+f"(acc[ma][na][1]),
                              "+f"(acc[ma][na][2]), "+f"(acc[ma][na][3])
                            : "r"(a[ma][0]), "r"(a[ma][1]), "r"(a[ma][2]), "r"(a[ma][3]),
                              "r"(bb.x), "r"(bb.y));
                    }
                }
            }
        }

        if (pf) {
            float4* swn = (float4*)(s_w + nxt * 5120);
#pragma unroll
            for (int j = 0; j < 5; j++) swn[tid + j * 256] = wreg[j];
            float* ssn = s_s + nxt * 2560;
#pragma unroll
            for (int s = 0; s < 9; s++) {
                int kkl = kq + 4 * s;
                int cc = kkl / 9, k = kkl - cc * 9;
                float4 wv = s_mw[sp * 9 + k];
                float v = wv.x * g0[s] + wv.y * g1[s] + wv.z * g2[s] + wv.w * g3[s];
                ssn[sp * KST + kpos(kkl)] = to_tf32(v);
            }
        }
        __syncthreads();
    }

#pragma unroll
    for (int ma = 0; ma < 2; ma++) {
        int prow = hw0 + m0 + ma * 16 + arow;
#pragma unroll
        for (int na = 0; na < 4; na++) {
            int o = n0 + na * 8 + 2 * acol;
            float b0 = __ldg(bias + o);
            float b1 = __ldg(bias + o + 1);
            float* p0 = out + ((size_t)b * Cout + o) * HW + prow;
            float* p1 = p0 + HW;
            p0[0] = acc[ma][na][0] + b0;
            p1[0] = acc[ma][na][1] + b1;
            p0[8] = acc[ma][na][2] + b0;
            p1[8] = acc[ma][na][3] + b1;
        }
    }
}

// ---------------- launcher ----------------
extern "C" void kernel_launch(void* const* d_in, const int* in_sizes, int n_in,
                              void* d_out, int out_size) {
    const float* x        = (const float*)d_in[0];
    const float* offset_w = (const float*)d_in[1];
    const float* offset_b = (const float*)d_in[2];
    const float* mod_w    = (const float*)d_in[3];
    const float* mod_b    = (const float*)d_in[4];
    const float* w        = (const float*)d_in[5];
    const float* bias     = (const float*)d_in[6];
    float* out = (float*)d_out;

    const int SMEM = 9216 + 9216 + 20480 + 40960;   // 79872 B
    cudaFuncSetAttribute(main_kernel, cudaFuncAttributeMaxDynamicSharedMemorySize, SMEM);

    prep_weights_kernel<<<(NCH * Cout * KP + 255) / 256, 256>>>(w, offset_w, mod_w);
    offmask_kernel<<<NPIX / 64, 256>>>(x, offset_b, mod_b);
    main_kernel<<<NPIX / 64, 256, SMEM>>>(x, bias, out);
}